// round 7
// baseline (speedup 1.0000x reference)
#include <cuda_runtime.h>
#include <cuda_bf16.h>

// QuadrupletMarginMiner dense-mask: out[i,j,k,n] = 96^4 booleans, emitted as
// float32 (1.0f / 0.0f) — the harness's output dtype for a bool reference.
//   sames[i,j] = share-label & i!=j ; diffs[i,n] = !share-label (diag kept)
//   viol[i,p,n] = (mat[i,n] - mat[i,p]) <= 0.3, mat = -cosine(logits, feat2)
//   out = sames[i,j] & sames[i,k] & (j<k) & diffs[i,n] & (viol[i,j,n]|viol[i,k,n])
// Strategy: tiny bitmask tables, then one store-bandwidth-bound expansion
// kernel (340 MB of float output, coalesced STG.128).

#define NB 96
#define DF 64
#define NC 21
#define MARGIN_F 0.3f

__device__ float    g_mat[NB][NB];        // 36 KB
__device__ unsigned g_viol[NB][NB][3];    // 96-bit viol mask per (i,p)
__device__ unsigned g_sames[NB][3];       // 96-bit sames mask per i
__device__ unsigned g_diff[NB][3];        // 96-bit diffs mask per i

// ---- kernel 1: cosine matrix + label bitmasks (96 blocks x 96 threads) ----
__global__ void k_mat(const float* __restrict__ logits,
                      const float* __restrict__ labels,
                      const float* __restrict__ feat2) {
    int i = blockIdx.x;
    int j = threadIdx.x;

    float nx = 0.f, ny = 0.f, dot = 0.f;
#pragma unroll
    for (int d = 0; d < DF; d++) {
        float a = logits[i * DF + d];
        float b = feat2[j * DF + d];
        nx += a * a;
        ny += b * b;
        dot += a * b;
    }
    float denom = fmaxf(sqrtf(nx), 1e-12f) * fmaxf(sqrtf(ny), 1e-12f);
    g_mat[i][j] = -(dot / denom);

    // share-a-label: dot of multi-hot rows > 0 (diagonal kept for diffs)
    float sdot = 0.f;
#pragma unroll
    for (int c = 0; c < NC; c++)
        sdot += labels[i * NC + c] * labels[j * NC + c];
    bool s = sdot > 0.f;

    unsigned bs = __ballot_sync(0xFFFFFFFFu, s && (j != i));  // sames: no diag
    unsigned bd = __ballot_sync(0xFFFFFFFFu, !s);             // diffs: diag kept
    if ((j & 31) == 0) {
        g_sames[i][j >> 5] = bs;
        g_diff[i][j >> 5]  = bd;
    }
}

// ---- kernel 2: violation bitmasks (96 blocks x 96 threads) ----
__global__ void k_viol() {
    int i = blockIdx.x;
    int p = threadIdx.x;
    __shared__ float sm[NB];
    sm[p] = g_mat[i][p];
    __syncthreads();

    float mp = sm[p];
    unsigned w0 = 0, w1 = 0, w2 = 0;
#pragma unroll
    for (int neg = 0; neg < 32; neg++)
        if ((sm[neg] - mp) <= MARGIN_F) w0 |= 1u << neg;
#pragma unroll
    for (int neg = 0; neg < 32; neg++)
        if ((sm[32 + neg] - mp) <= MARGIN_F) w1 |= 1u << neg;
#pragma unroll
    for (int neg = 0; neg < 32; neg++)
        if ((sm[64 + neg] - mp) <= MARGIN_F) w2 |= 1u << neg;

    g_viol[i][p][0] = w0;
    g_viol[i][p][1] = w1;
    g_viol[i][p][2] = w2;
}

// ---- kernel 3: expand masks -> 340 MB float output ----
// block = (i,j) pair (9216 blocks, 9216 floats = 2304 float4 each).
// 768 threads x 3 iterations; iteration s: thread writes float4 #(s*768+tid).
// quad index g -> k = g/24 (24 float4 per 96-float n-row), q = g%24,
// word w = q/8, nibble = bits [4*(q%8) .. +3] of the row mask.
// Consecutive tid -> consecutive 16B: fully coalesced STG.128.
__global__ __launch_bounds__(768) void k_out(float4* __restrict__ out) {
    int i = blockIdx.x / NB;
    int j = blockIdx.x % NB;

    unsigned sij = (g_sames[i][j >> 5] >> (j & 31)) & 1u;
    unsigned vj0 = g_viol[i][j][0], vj1 = g_viol[i][j][1], vj2 = g_viol[i][j][2];
    unsigned d0 = g_diff[i][0], d1 = g_diff[i][1], d2 = g_diff[i][2];
    // pre-AND diffs into vj contribution: row_w = d_w & (vj_w | vk_w)
    //                                           = (d_w & vj_w) | (d_w & vk_w)
    unsigned dj0 = d0 & vj0, dj1 = d1 & vj1, dj2 = d2 & vj2;

    float4* base = out + (size_t)blockIdx.x * (NB * NB / 4);

#pragma unroll
    for (int s = 0; s < 3; s++) {
        int g = s * 768 + threadIdx.x;
        int k = g / 24;
        int q = g - k * 24;

        unsigned m = 0u;
        if (sij && (j < k) && ((g_sames[i][k >> 5] >> (k & 31)) & 1u)) {
            int w = q >> 3;
            unsigned vk = g_viol[i][k][w];
            unsigned dw = (w == 0) ? d0 : ((w == 1) ? d1 : d2);
            unsigned dj = (w == 0) ? dj0 : ((w == 1) ? dj1 : dj2);
            m = (dj | (dw & vk)) >> ((q & 7) * 4);
        }

        float4 r;
        r.x = __uint_as_float((m & 1u) ? 0x3F800000u : 0u);
        r.y = __uint_as_float((m & 2u) ? 0x3F800000u : 0u);
        r.z = __uint_as_float((m & 4u) ? 0x3F800000u : 0u);
        r.w = __uint_as_float((m & 8u) ? 0x3F800000u : 0u);
        base[g] = r;
    }
}

extern "C" void kernel_launch(void* const* d_in, const int* in_sizes, int n_in,
                              void* d_out, int out_size) {
    const float* logits = (const float*)d_in[0];  // [96, 64]
    const float* labels = (const float*)d_in[1];  // [96, 21]
    const float* feat2  = (const float*)d_in[2];  // [96, 64]

    k_mat<<<NB, NB>>>(logits, labels, feat2);
    k_viol<<<NB, NB>>>();
    k_out<<<NB * NB, 768>>>((float4*)d_out);
}

// round 8
// speedup vs baseline: 1.1668x; 1.1668x over previous
#include <cuda_runtime.h>
#include <cuda_bf16.h>

// QuadrupletMarginMiner dense-mask: out[i,j,k,n] = 96^4 booleans as float32.
//   sames[i,j] = share-label & i!=j ; diffs[i,n] = !share-label (diag kept)
//   viol[i,p,n] = (mat[i,n] - mat[i,p]) <= 0.3, mat = -cosine(logits, feat2)
//   out = sames[i,j] & sames[i,k] & (j<k) & diffs[i,n] & (viol[i,j,n]|viol[i,k,n])
// One fused precompute kernel (bitmask tables), then one store-bandwidth-bound
// expansion kernel (340 MB float output, streaming STG.128).

#define NB 96
#define DF 64
#define NC 21
#define MARGIN_F 0.3f

__device__ unsigned g_viol[NB][NB][3];    // 96-bit viol mask per (i,p)
__device__ unsigned g_sames[NB][3];       // 96-bit sames mask per i
__device__ unsigned g_diff[NB][3];        // 96-bit diffs mask per i

// ---- fused precompute: cosine row -> shared -> viol masks + label masks ----
// 96 blocks (i) x 96 threads (j). Block i owns mat row i entirely, so the
// violation masks for row i are built in-block with no global round-trip.
__global__ __launch_bounds__(NB) void k_pre(const float* __restrict__ logits,
                                            const float* __restrict__ labels,
                                            const float* __restrict__ feat2) {
    int i = blockIdx.x;
    int j = threadIdx.x;
    __shared__ float sm[NB];

    float nx = 0.f, ny = 0.f, dot = 0.f;
#pragma unroll
    for (int d = 0; d < DF; d++) {
        float a = logits[i * DF + d];   // broadcast across block (L1 hit)
        float b = feat2[j * DF + d];
        nx += a * a;
        ny += b * b;
        dot += a * b;
    }
    float denom = fmaxf(sqrtf(nx), 1e-12f) * fmaxf(sqrtf(ny), 1e-12f);
    sm[j] = -(dot / denom);

    // share-a-label: dot of multi-hot rows > 0 (diagonal kept for diffs)
    float sdot = 0.f;
#pragma unroll
    for (int c = 0; c < NC; c++)
        sdot += labels[i * NC + c] * labels[j * NC + c];
    bool s = sdot > 0.f;

    unsigned bs = __ballot_sync(0xFFFFFFFFu, s && (j != i));  // sames: no diag
    unsigned bd = __ballot_sync(0xFFFFFFFFu, !s);             // diffs: diag kept
    if ((j & 31) == 0) {
        g_sames[i][j >> 5] = bs;
        g_diff[i][j >> 5]  = bd;
    }

    __syncthreads();

    float mp = sm[j];
    unsigned w0 = 0, w1 = 0, w2 = 0;
#pragma unroll
    for (int neg = 0; neg < 32; neg++)
        if ((sm[neg] - mp) <= MARGIN_F) w0 |= 1u << neg;
#pragma unroll
    for (int neg = 0; neg < 32; neg++)
        if ((sm[32 + neg] - mp) <= MARGIN_F) w1 |= 1u << neg;
#pragma unroll
    for (int neg = 0; neg < 32; neg++)
        if ((sm[64 + neg] - mp) <= MARGIN_F) w2 |= 1u << neg;

    g_viol[i][j][0] = w0;
    g_viol[i][j][1] = w1;
    g_viol[i][j][2] = w2;
}

// ---- expand masks -> 340 MB float output ----
// block = (i,j) pair (9216 blocks, 9216 floats = 2304 float4 each).
// 768 threads x 3 iterations; iteration s: thread writes float4 #(s*768+tid).
// quad index g -> k = g/24 (24 float4 per 96-float n-row), q = g%24,
// word w = q/8, nibble = bits [4*(q%8) .. +3] of the row mask.
// Consecutive tid -> consecutive 16B: fully coalesced streaming STG.128.
__global__ __launch_bounds__(768) void k_out(float4* __restrict__ out) {
    int i = blockIdx.x / NB;
    int j = blockIdx.x % NB;

    unsigned sij = (g_sames[i][j >> 5] >> (j & 31)) & 1u;
    unsigned vj0 = g_viol[i][j][0], vj1 = g_viol[i][j][1], vj2 = g_viol[i][j][2];
    unsigned d0 = g_diff[i][0], d1 = g_diff[i][1], d2 = g_diff[i][2];
    // row_w = d_w & (vj_w | vk_w) = (d_w & vj_w) | (d_w & vk_w)
    unsigned dj0 = d0 & vj0, dj1 = d1 & vj1, dj2 = d2 & vj2;

    float4* base = out + (size_t)blockIdx.x * (NB * NB / 4);

#pragma unroll
    for (int s = 0; s < 3; s++) {
        int g = s * 768 + threadIdx.x;
        int k = g / 24;
        int q = g - k * 24;

        unsigned m = 0u;
        if (sij && (j < k) && ((g_sames[i][k >> 5] >> (k & 31)) & 1u)) {
            int w = q >> 3;
            unsigned vk = g_viol[i][k][w];
            unsigned dw = (w == 0) ? d0 : ((w == 1) ? d1 : d2);
            unsigned dj = (w == 0) ? dj0 : ((w == 1) ? dj1 : dj2);
            m = (dj | (dw & vk)) >> ((q & 7) * 4);
        }

        float4 r;
        r.x = __uint_as_float((m & 1u) ? 0x3F800000u : 0u);
        r.y = __uint_as_float((m & 2u) ? 0x3F800000u : 0u);
        r.z = __uint_as_float((m & 4u) ? 0x3F800000u : 0u);
        r.w = __uint_as_float((m & 8u) ? 0x3F800000u : 0u);
        __stcs(base + g, r);   // evict-first: write-once streaming data
    }
}

extern "C" void kernel_launch(void* const* d_in, const int* in_sizes, int n_in,
                              void* d_out, int out_size) {
    const float* logits = (const float*)d_in[0];  // [96, 64]
    const float* labels = (const float*)d_in[1];  // [96, 21]
    const float* feat2  = (const float*)d_in[2];  // [96, 64]

    k_pre<<<NB, NB>>>(logits, labels, feat2);
    k_out<<<NB * NB, 768>>>((float4*)d_out);
}

// round 9
// speedup vs baseline: 1.2478x; 1.0694x over previous
#include <cuda_runtime.h>
#include <cuda_bf16.h>

// QuadrupletMarginMiner dense-mask: out[i,j,k,n] = 96^4 booleans as float32.
//   sames[i,j] = share-label & i!=j ; diffs[i,n] = !share-label (diag kept)
//   viol[i,p,n] = (mat[i,n] - mat[i,p]) <= 0.3, mat = -cosine(logits, feat2)
//   out = sames[i,j] & sames[i,k] & (j<k) & diffs[i,n] & (viol[i,j,n]|viol[i,k,n])
// One fused precompute kernel (bitmask tables), then one store-bandwidth-bound
// expansion kernel (340 MB float output, streaming STG.128, all index math
// hoisted out of the store loop).

#define NB 96
#define DF 64
#define NC 21
#define MARGIN_F 0.3f

__device__ unsigned g_viol[NB][NB][3];    // 96-bit viol mask per (i,p)
__device__ unsigned g_sames[NB][3];       // 96-bit sames mask per i
__device__ unsigned g_diff[NB][3];        // 96-bit diffs mask per i

// ---- fused precompute: cosine row -> shared -> viol masks + label masks ----
__global__ __launch_bounds__(NB) void k_pre(const float* __restrict__ logits,
                                            const float* __restrict__ labels,
                                            const float* __restrict__ feat2) {
    int i = blockIdx.x;
    int j = threadIdx.x;
    __shared__ float sm[NB];

    float nx = 0.f, ny = 0.f, dot = 0.f;
#pragma unroll
    for (int d = 0; d < DF; d++) {
        float a = logits[i * DF + d];   // broadcast across block (L1 hit)
        float b = feat2[j * DF + d];
        nx += a * a;
        ny += b * b;
        dot += a * b;
    }
    float denom = fmaxf(sqrtf(nx), 1e-12f) * fmaxf(sqrtf(ny), 1e-12f);
    sm[j] = -(dot / denom);

    float sdot = 0.f;
#pragma unroll
    for (int c = 0; c < NC; c++)
        sdot += labels[i * NC + c] * labels[j * NC + c];
    bool s = sdot > 0.f;

    unsigned bs = __ballot_sync(0xFFFFFFFFu, s && (j != i));  // sames: no diag
    unsigned bd = __ballot_sync(0xFFFFFFFFu, !s);             // diffs: diag kept
    if ((j & 31) == 0) {
        g_sames[i][j >> 5] = bs;
        g_diff[i][j >> 5]  = bd;
    }

    __syncthreads();

    float mp = sm[j];
    unsigned w0 = 0, w1 = 0, w2 = 0;
#pragma unroll
    for (int neg = 0; neg < 32; neg++)
        if ((sm[neg] - mp) <= MARGIN_F) w0 |= 1u << neg;
#pragma unroll
    for (int neg = 0; neg < 32; neg++)
        if ((sm[32 + neg] - mp) <= MARGIN_F) w1 |= 1u << neg;
#pragma unroll
    for (int neg = 0; neg < 32; neg++)
        if ((sm[64 + neg] - mp) <= MARGIN_F) w2 |= 1u << neg;

    g_viol[i][j][0] = w0;
    g_viol[i][j][1] = w1;
    g_viol[i][j][2] = w2;
}

// ---- expand masks -> 340 MB float output ----
// grid (j, i); block = one (i,j) pair = 9216 floats = 2304 float4.
// 768 threads: k = tid>>3 (fixed per thread!), sub = tid&7.
// Iteration s writes quad k*24 + s*8 + sub; mask word w == s, nibble == sub.
// => guard, viol[i][k] loads, and nibble shift all hoist out of the loop;
// body is SHF+AND+4xSEL+STG.128. 8-thread groups store contiguous aligned
// 128B segments (full lines), streaming (.cs).
__global__ __launch_bounds__(768) void k_out(float4* __restrict__ out) {
    int j = blockIdx.x;
    int i = blockIdx.y;
    int tid = threadIdx.x;
    int k   = tid >> 3;
    int sub = tid & 7;
    int shift = sub * 4;

    unsigned sij = (g_sames[i][j >> 5] >> (j & 31)) & 1u;
    unsigned sik = (g_sames[i][k >> 5] >> (k & 31)) & 1u;

    unsigned m0 = 0u, m1 = 0u, m2 = 0u;
    if (sij & sik & (unsigned)(j < k)) {
        unsigned r0 = g_diff[i][0] & (g_viol[i][j][0] | g_viol[i][k][0]);
        unsigned r1 = g_diff[i][1] & (g_viol[i][j][1] | g_viol[i][k][1]);
        unsigned r2 = g_diff[i][2] & (g_viol[i][j][2] | g_viol[i][k][2]);
        m0 = (r0 >> shift) & 0xFu;
        m1 = (r1 >> shift) & 0xFu;
        m2 = (r2 >> shift) & 0xFu;
    }

    float4* base = out + (size_t)(i * NB + j) * (NB * NB / 4) + k * 24 + sub;

    const float ONE = 1.0f, ZERO = 0.0f;
    float4 q0, q1, q2;
    q0.x = (m0 & 1u) ? ONE : ZERO;  q0.y = (m0 & 2u) ? ONE : ZERO;
    q0.z = (m0 & 4u) ? ONE : ZERO;  q0.w = (m0 & 8u) ? ONE : ZERO;
    q1.x = (m1 & 1u) ? ONE : ZERO;  q1.y = (m1 & 2u) ? ONE : ZERO;
    q1.z = (m1 & 4u) ? ONE : ZERO;  q1.w = (m1 & 8u) ? ONE : ZERO;
    q2.x = (m2 & 1u) ? ONE : ZERO;  q2.y = (m2 & 2u) ? ONE : ZERO;
    q2.z = (m2 & 4u) ? ONE : ZERO;  q2.w = (m2 & 8u) ? ONE : ZERO;

    __stcs(base,      q0);   // n-word 0 (s=0): quads k*24 + 0*8 + sub
    __stcs(base + 8,  q1);   // n-word 1 (s=1)
    __stcs(base + 16, q2);   // n-word 2 (s=2)
}

extern "C" void kernel_launch(void* const* d_in, const int* in_sizes, int n_in,
                              void* d_out, int out_size) {
    const float* logits = (const float*)d_in[0];  // [96, 64]
    const float* labels = (const float*)d_in[1];  // [96, 21]
    const float* feat2  = (const float*)d_in[2];  // [96, 64]

    k_pre<<<NB, NB>>>(logits, labels, feat2);
    k_out<<<dim3(NB, NB), 768>>>((float4*)d_out);
}